// round 2
// baseline (speedup 1.0000x reference)
#include <cuda_runtime.h>
#include <cuda_bf16.h>
#include <cstdint>
#include <math.h>

#define INST   64
#define NVOCAB 128
#define ED     256
#define HID    1024
#define BATCH  2048

// Precomputed HL[i] = E_l[i] @ W1[i], HR[i] = E_r[i] @ W1[i]  (fp32 scratch)
__device__ float g_HL[INST * NVOCAB * HID];
__device__ float g_HR[INST * NVOCAB * HID];

__device__ __forceinline__ uint32_t f2tf(float f) {
    uint32_t u;
    asm("cvt.rna.tf32.f32 %0, %1;" : "=r"(u) : "f"(f));
    return u;
}

__device__ __forceinline__ void mma8(float* c, const uint32_t* a, const uint32_t* b) {
    asm volatile(
        "mma.sync.aligned.m16n8k8.row.col.f32.tf32.tf32.f32 "
        "{%0,%1,%2,%3}, {%4,%5,%6,%7}, {%8,%9}, {%0,%1,%2,%3};"
        : "+f"(c[0]), "+f"(c[1]), "+f"(c[2]), "+f"(c[3])
        : "r"(a[0]), "r"(a[1]), "r"(a[2]), "r"(a[3]), "r"(b[0]), "r"(b[1]));
}

__device__ __forceinline__ float gelu_exact(float x) {
    return 0.5f * x * (1.0f + erff(x * 0.7071067811865476f));
}

// Shared tile strides (words). Conflict-free fragment loads:
//   A bank = (4*row + k) % 32, B bank = (8*k + n) % 32
#define ASTR 36
#define BSTR 136
#define ASZ (128 * ASTR)
#define BSZ (32 * BSTR)
#define SMEM_WORDS (2 * ASZ + 2 * BSZ)
#define SMEM_BYTES (SMEM_WORDS * 4)

__device__ __forceinline__ uint4 tf4(float4 v) {
    return make_uint4(f2tf(v.x), f2tf(v.y), f2tf(v.z), f2tf(v.w));
}
__device__ __forceinline__ uint4 gelu4(float4 l, float4 r) {
    uint4 u;
    u.x = f2tf(gelu_exact(l.x + r.x));
    u.y = f2tf(gelu_exact(l.y + r.y));
    u.z = f2tf(gelu_exact(l.z + r.z));
    u.w = f2tf(gelu_exact(l.w + r.w));
    return u;
}

// Shared compute phase: 4 k-slices of 8, 16 MMAs each.
#define COMPUTE_TILE(Ap, Bp)                                                    \
    _Pragma("unroll")                                                           \
    for (int ks = 0; ks < 4; ks++) {                                            \
        const int kk = ks * 8;                                                  \
        uint32_t af[2][4];                                                      \
        _Pragma("unroll")                                                       \
        for (int s = 0; s < 2; s++) {                                           \
            int r0 = wm + s * 16 + g;                                           \
            af[s][0] = (Ap)[r0 * ASTR + kk + tg];                               \
            af[s][1] = (Ap)[(r0 + 8) * ASTR + kk + tg];                         \
            af[s][2] = (Ap)[r0 * ASTR + kk + 4 + tg];                           \
            af[s][3] = (Ap)[(r0 + 8) * ASTR + kk + 4 + tg];                     \
        }                                                                       \
        uint32_t bf[8][2];                                                      \
        _Pragma("unroll")                                                       \
        for (int q = 0; q < 8; q++) {                                           \
            int nb = wn + q * 8 + g;                                            \
            bf[q][0] = (Bp)[(kk + tg) * BSTR + nb];                             \
            bf[q][1] = (Bp)[(kk + 4 + tg) * BSTR + nb];                         \
        }                                                                       \
        _Pragma("unroll")                                                       \
        for (int s = 0; s < 2; s++)                                             \
            _Pragma("unroll")                                                   \
            for (int q = 0; q < 8; q++)                                         \
                mma8(c[s][q], af[s], bf[q]);                                    \
    }

// ---------------------------------------------------------------------------
// Phase 1: HL/HR[i] = E[i] (128x256) @ W1[i] (256x1024), tf32 MMA, fp32 out
// Software-pipelined, double-buffered. grid (8, 64, 2), 256 threads.
// ---------------------------------------------------------------------------
__global__ __launch_bounds__(256, 2) void phase1_kernel(
    const float* __restrict__ El, const float* __restrict__ Er,
    const float* __restrict__ W1)
{
    extern __shared__ uint32_t smem[];
    uint32_t* A0 = smem;
    uint32_t* A1 = smem + ASZ;
    uint32_t* B0 = smem + 2 * ASZ;
    uint32_t* B1 = smem + 2 * ASZ + BSZ;

    const int nt = blockIdx.x, inst = blockIdx.y, side = blockIdx.z;
    const float* E   = (side ? Er : El) + inst * NVOCAB * ED;
    float*       Hst = (side ? g_HR : g_HL) + inst * NVOCAB * HID + nt * 128;
    const float* W   = W1 + inst * ED * HID + nt * 128;

    const int t    = threadIdx.x;
    const int lane = t & 31, w = t >> 5;
    const int wm = (w & 3) * 32, wn = (w >> 2) * 64;
    const int g = lane >> 2, tg = lane & 3;
    const int r = t >> 1, h = t & 1;
    const int kB = t >> 5, ncB = (t & 31) * 4;

    const float* pE = E + r * ED + h * 16;
    const float* pW = W + kB * HID + ncB;
    const int aoff = r * ASTR + h * 16;
    const int boff = kB * BSTR + ncB;

    float c[2][8][4];
#pragma unroll
    for (int s = 0; s < 2; s++)
#pragma unroll
        for (int q = 0; q < 8; q++)
#pragma unroll
            for (int v = 0; v < 4; v++) c[s][q][v] = 0.f;

    float4 sa[4], sb[4];
#define P1_LOAD(KT) {                                                           \
        const int k0 = (KT) * 32;                                               \
        _Pragma("unroll")                                                       \
        for (int j = 0; j < 4; j++)                                             \
            sa[j] = *reinterpret_cast<const float4*>(pE + k0 + 4 * j);          \
        _Pragma("unroll")                                                       \
        for (int j = 0; j < 4; j++)                                             \
            sb[j] = *reinterpret_cast<const float4*>(pW + (size_t)(k0 + 8 * j) * HID); \
    }
#define P1_STEP(KT, Ap, Bp) {                                                   \
        _Pragma("unroll")                                                       \
        for (int j = 0; j < 4; j++)                                             \
            *reinterpret_cast<uint4*>(&(Ap)[aoff + 4 * j]) = tf4(sa[j]);        \
        _Pragma("unroll")                                                       \
        for (int j = 0; j < 4; j++)                                             \
            *reinterpret_cast<uint4*>(&(Bp)[boff + 8 * j * BSTR]) = tf4(sb[j]); \
        __syncthreads();                                                        \
        int knext = ((KT) + 1 < ED / 32) ? (KT) + 1 : 0;                        \
        P1_LOAD(knext);                                                         \
        COMPUTE_TILE(Ap, Bp);                                                   \
        __syncthreads();                                                        \
    }

    P1_LOAD(0);
#pragma unroll 1
    for (int kt = 0; kt < ED / 32; kt += 2) {
        P1_STEP(kt, A0, B0);
        P1_STEP(kt + 1, A1, B1);
    }

#pragma unroll
    for (int s = 0; s < 2; s++) {
        int row = wm + s * 16 + g;
#pragma unroll
        for (int q = 0; q < 8; q++) {
            int col = wn + q * 8 + 2 * tg;
            *reinterpret_cast<float2*>(Hst + row * HID + col) =
                make_float2(c[s][q][0], c[s][q][1]);
            *reinterpret_cast<float2*>(Hst + (row + 8) * HID + col) =
                make_float2(c[s][q][2], c[s][q][3]);
        }
    }
}

// ---------------------------------------------------------------------------
// Phase 2: out[b,i,:] = gelu(HL[i,a1[b],:] + HR[i,a2[b],:]) @ W2[i]
// Fused gather + add + exact gelu + tf32, pipelined & double-buffered.
// grid (16 m-tiles, 64 instances), 256 threads
// ---------------------------------------------------------------------------
__global__ __launch_bounds__(256, 2) void phase2_kernel(
    const int* __restrict__ a, const float* __restrict__ W2,
    float* __restrict__ out)
{
    extern __shared__ uint32_t smem[];
    uint32_t* A0 = smem;
    uint32_t* A1 = smem + ASZ;
    uint32_t* B0 = smem + 2 * ASZ;
    uint32_t* B1 = smem + 2 * ASZ + BSZ;

    const int mt = blockIdx.x, inst = blockIdx.y;
    const float* W = W2 + inst * HID * NVOCAB;

    const int t    = threadIdx.x;
    const int lane = t & 31, w = t >> 5;
    const int wm = (w & 3) * 32, wn = (w >> 2) * 64;
    const int g = lane >> 2, tg = lane & 3;
    const int r = t >> 1, h = t & 1;
    const int kB = t >> 5, ncB = (t & 31) * 4;

    const int b  = mt * 128 + r;
    const int i1 = a[2 * b];
    const int i2 = a[2 * b + 1];
    const float* pL = g_HL + ((size_t)inst * NVOCAB + i1) * HID + h * 16;
    const float* pR = g_HR + ((size_t)inst * NVOCAB + i2) * HID + h * 16;
    const float* pW = W + kB * NVOCAB + ncB;
    const int aoff = r * ASTR + h * 16;
    const int boff = kB * BSTR + ncB;

    float c[2][8][4];
#pragma unroll
    for (int s = 0; s < 2; s++)
#pragma unroll
        for (int q = 0; q < 8; q++)
#pragma unroll
            for (int v = 0; v < 4; v++) c[s][q][v] = 0.f;

    float4 sl[4], sr[4], sb[4];
#define P2_LOAD(KT) {                                                           \
        const int k0 = (KT) * 32;                                               \
        _Pragma("unroll")                                                       \
        for (int j = 0; j < 4; j++) {                                           \
            sl[j] = *reinterpret_cast<const float4*>(pL + k0 + 4 * j);          \
            sr[j] = *reinterpret_cast<const float4*>(pR + k0 + 4 * j);          \
        }                                                                       \
        _Pragma("unroll")                                                       \
        for (int j = 0; j < 4; j++)                                             \
            sb[j] = *reinterpret_cast<const float4*>(pW + (size_t)(k0 + 8 * j) * NVOCAB); \
    }
#define P2_STEP(KT, Ap, Bp) {                                                   \
        _Pragma("unroll")                                                       \
        for (int j = 0; j < 4; j++)                                             \
            *reinterpret_cast<uint4*>(&(Ap)[aoff + 4 * j]) = gelu4(sl[j], sr[j]); \
        _Pragma("unroll")                                                       \
        for (int j = 0; j < 4; j++)                                             \
            *reinterpret_cast<uint4*>(&(Bp)[boff + 8 * j * BSTR]) = tf4(sb[j]); \
        __syncthreads();                                                        \
        int knext = ((KT) + 1 < HID / 32) ? (KT) + 1 : 0;                       \
        P2_LOAD(knext);                                                         \
        COMPUTE_TILE(Ap, Bp);                                                   \
        __syncthreads();                                                        \
    }

    P2_LOAD(0);
#pragma unroll 1
    for (int kt = 0; kt < HID / 32; kt += 2) {
        P2_STEP(kt, A0, B0);
        P2_STEP(kt + 1, A1, B1);
    }

    // Epilogue: out shape (BATCH, INST, NVOCAB) fp32
#pragma unroll
    for (int s = 0; s < 2; s++) {
        int rowb = mt * 128 + wm + s * 16 + g;
#pragma unroll
        for (int q = 0; q < 8; q++) {
            int col = wn + q * 8 + 2 * tg;
            *reinterpret_cast<float2*>(out + ((size_t)rowb * INST + inst) * NVOCAB + col) =
                make_float2(c[s][q][0], c[s][q][1]);
            *reinterpret_cast<float2*>(out + ((size_t)(rowb + 8) * INST + inst) * NVOCAB + col) =
                make_float2(c[s][q][2], c[s][q][3]);
        }
    }
}

extern "C" void kernel_launch(void* const* d_in, const int* in_sizes, int n_in,
                              void* d_out, int out_size)
{
    const int*   a  = (const int*)d_in[0];
    const float* El = (const float*)d_in[1];
    const float* Er = (const float*)d_in[2];
    const float* W1 = (const float*)d_in[3];
    const float* W2 = (const float*)d_in[4];
    float* out = (float*)d_out;

    static int configured = 0;
    if (!configured) {
        cudaFuncSetAttribute(phase1_kernel,
                             cudaFuncAttributeMaxDynamicSharedMemorySize, SMEM_BYTES);
        cudaFuncSetAttribute(phase2_kernel,
                             cudaFuncAttributeMaxDynamicSharedMemorySize, SMEM_BYTES);
        configured = 1;
    }

    dim3 g1(HID / 128, INST, 2);     // 8 n-tiles x 64 instances x {L,R}
    phase1_kernel<<<g1, 256, SMEM_BYTES>>>(El, Er, W1);

    dim3 g2(BATCH / 128, INST);      // 16 m-tiles x 64 instances
    phase2_kernel<<<g2, 256, SMEM_BYTES>>>(a, W2, out);
}

// round 4
// speedup vs baseline: 1.7497x; 1.7497x over previous
#include <cuda_runtime.h>
#include <cuda_bf16.h>
#include <cstdint>
#include <math.h>

#define INST   64
#define NVOCAB 128
#define ED     256
#define HID    1024
#define BATCH  2048

// Precomputed HL[i] = E_l[i] @ W1[i], HR[i] = E_r[i] @ W1[i]  (fp32 scratch)
__device__ float g_HL[INST * NVOCAB * HID];
__device__ float g_HR[INST * NVOCAB * HID];
// W2 preconverted to tf32 bit patterns, layout [inst][k][n] (same as input)
__device__ uint32_t g_W2t[INST * HID * NVOCAB];

__device__ __forceinline__ uint32_t f2tf(float f) {
    uint32_t u;
    asm("cvt.rna.tf32.f32 %0, %1;" : "=r"(u) : "f"(f));
    return u;
}
__device__ __forceinline__ void mma8(float* c, const uint32_t* a, const uint32_t* b) {
    asm volatile(
        "mma.sync.aligned.m16n8k8.row.col.f32.tf32.tf32.f32 "
        "{%0,%1,%2,%3}, {%4,%5,%6,%7}, {%8,%9}, {%0,%1,%2,%3};"
        : "+f"(c[0]), "+f"(c[1]), "+f"(c[2]), "+f"(c[3])
        : "r"(a[0]), "r"(a[1]), "r"(a[2]), "r"(a[3]), "r"(b[0]), "r"(b[1]));
}
__device__ __forceinline__ float gelu_exact(float x) {
    return 0.5f * x * (1.0f + erff(x * 0.7071067811865476f));
}
__device__ __forceinline__ uint32_t smem_u32(const void* p) {
    uint32_t a;
    asm("{ .reg .u64 t; cvta.to.shared.u64 t, %1; cvt.u32.u64 %0, t; }" : "=r"(a) : "l"(p));
    return a;
}

// Shared tile strides (words). Conflict-free fragment loads:
//   A bank = (4*row + k) % 32, B bank = (8*k + n) % 32
#define ASTR 36
#define BSTR 136
#define ASZW (128 * ASTR)     // 4608 words
#define BSZW (32 * BSTR)      // 4352 words
#define NKT  (HID / 32)       // 32 k-tiles in phase 2

// 16 MMAs per 8-deep k-slice, 4 slices per 32-K tile.
#define COMPUTE_TILE(Ap, Bp)                                                    \
    _Pragma("unroll")                                                           \
    for (int ks = 0; ks < 4; ks++) {                                            \
        const int kk = ks * 8;                                                  \
        uint32_t af[2][4];                                                      \
        _Pragma("unroll")                                                       \
        for (int s = 0; s < 2; s++) {                                           \
            int r0 = wm + s * 16 + g;                                           \
            af[s][0] = (Ap)[r0 * ASTR + kk + tg];                               \
            af[s][1] = (Ap)[(r0 + 8) * ASTR + kk + tg];                         \
            af[s][2] = (Ap)[r0 * ASTR + kk + 4 + tg];                           \
            af[s][3] = (Ap)[(r0 + 8) * ASTR + kk + 4 + tg];                     \
        }                                                                       \
        uint32_t bf[8][2];                                                      \
        _Pragma("unroll")                                                       \
        for (int q = 0; q < 8; q++) {                                           \
            int nb = wn + q * 8 + g;                                            \
            bf[q][0] = (Bp)[(kk + tg) * BSTR + nb];                             \
            bf[q][1] = (Bp)[(kk + 4 + tg) * BSTR + nb];                         \
        }                                                                       \
        _Pragma("unroll")                                                       \
        for (int s = 0; s < 2; s++)                                             \
            _Pragma("unroll")                                                   \
            for (int q = 0; q < 8; q++)                                         \
                mma8(c[s][q], af[s], bf[q]);                                    \
    }

// ---------------------------------------------------------------------------
// Phase 0: W2 fp32 -> tf32 bit patterns (one-time, DRAM-bound ~10us)
// ---------------------------------------------------------------------------
__global__ __launch_bounds__(256) void w2t_kernel(const float* __restrict__ W2)
{
    size_t idx = ((size_t)blockIdx.x * 256 + threadIdx.x) * 4;
    float4 v = *reinterpret_cast<const float4*>(W2 + idx);
    *reinterpret_cast<uint4*>(g_W2t + idx) =
        make_uint4(f2tf(v.x), f2tf(v.y), f2tf(v.z), f2tf(v.w));
}

// ---------------------------------------------------------------------------
// Phase 1: HL/HR[i] = E[i] (128x256) @ W1[i] (256x1024), tf32 MMA, fp32 out
// Dynamic smem so 2 CTAs/SM fit. grid (8, 64, 2), 256 threads.
// ---------------------------------------------------------------------------
#define P1_SMEM ((ASZW + BSZW) * 4)
__global__ __launch_bounds__(256, 2) void phase1_kernel(
    const float* __restrict__ El, const float* __restrict__ Er,
    const float* __restrict__ W1)
{
    extern __shared__ uint32_t dsm[];
    uint32_t* A_s = dsm;
    uint32_t* B_s = dsm + ASZW;

    const int nt = blockIdx.x, inst = blockIdx.y, side = blockIdx.z;
    const float* E   = (side ? Er : El) + inst * NVOCAB * ED;
    float*       Hst = (side ? g_HR : g_HL) + inst * NVOCAB * HID + nt * 128;
    const float* W   = W1 + inst * ED * HID + nt * 128;

    const int t    = threadIdx.x;
    const int lane = t & 31, w = t >> 5;
    const int wm = (w & 3) * 32, wn = (w >> 2) * 64;
    const int g = lane >> 2, tg = lane & 3;
    const int r = t >> 1, h = t & 1;

    float c[2][8][4];
#pragma unroll
    for (int s = 0; s < 2; s++)
#pragma unroll
        for (int q = 0; q < 8; q++)
#pragma unroll
            for (int v = 0; v < 4; v++) c[s][q][v] = 0.f;

    for (int kt = 0; kt < ED / 32; kt++) {
        const int k0 = kt * 32;
#pragma unroll
        for (int j = 0; j < 4; j++) {
            float4 v = *reinterpret_cast<const float4*>(E + r * ED + k0 + h * 16 + 4 * j);
            uint4 u = make_uint4(f2tf(v.x), f2tf(v.y), f2tf(v.z), f2tf(v.w));
            *reinterpret_cast<uint4*>(&A_s[r * ASTR + h * 16 + 4 * j]) = u;
        }
#pragma unroll
        for (int j = 0; j < 4; j++) {
            int id = t + 256 * j;
            int k = id >> 5, nc = (id & 31) * 4;
            float4 v = *reinterpret_cast<const float4*>(W + (k0 + k) * HID + nc);
            uint4 u = make_uint4(f2tf(v.x), f2tf(v.y), f2tf(v.z), f2tf(v.w));
            *reinterpret_cast<uint4*>(&B_s[k * BSTR + nc]) = u;
        }
        __syncthreads();
        COMPUTE_TILE(A_s, B_s);
        __syncthreads();
    }

#pragma unroll
    for (int s = 0; s < 2; s++) {
        int row = wm + s * 16 + g;
#pragma unroll
        for (int q = 0; q < 8; q++) {
            int col = wn + q * 8 + 2 * tg;
            *reinterpret_cast<float2*>(Hst + row * HID + col) =
                make_float2(c[s][q][0], c[s][q][1]);
            *reinterpret_cast<float2*>(Hst + (row + 8) * HID + col) =
                make_float2(c[s][q][2], c[s][q][3]);
        }
    }
}

// ---------------------------------------------------------------------------
// Phase 2: out[b,i,:] = gelu(HL[i,a1[b],:] + HR[i,a2[b],:]) @ W2[i]
// A produced in-kernel (gather+add+erf gelu+tf32); B (pre-tf32) streamed via
// cp.async into a double-buffered stage, 2 groups in flight.
// grid (16 m-tiles, 64 instances), 256 threads, 2 CTAs/SM.
// ---------------------------------------------------------------------------
#define P2_SMEM ((ASZW + 2 * BSZW) * 4)   // 53248 bytes

__global__ __launch_bounds__(256, 2) void phase2_kernel(
    const int* __restrict__ a, float* __restrict__ out)
{
    extern __shared__ uint32_t dsm[];
    uint32_t* A_s = dsm;
    uint32_t* Bs  = dsm + ASZW;                 // two stages of BSZW
    const uint32_t bs_base = smem_u32(Bs);

    const int mt = blockIdx.x, inst = blockIdx.y;
    const uint32_t* Wt = g_W2t + (size_t)inst * HID * NVOCAB;

    const int t    = threadIdx.x;
    const int lane = t & 31, w = t >> 5;
    const int wm = (w & 3) * 32, wn = (w >> 2) * 64;
    const int g = lane >> 2, tg = lane & 3;
    const int r = t >> 1, h = t & 1;

    const int b  = mt * 128 + r;
    const int i1 = a[2 * b];
    const int i2 = a[2 * b + 1];
    const float* pL = g_HL + ((size_t)inst * NVOCAB + i1) * HID + h * 16;
    const float* pR = g_HR + ((size_t)inst * NVOCAB + i2) * HID + h * 16;
    const int aoff = r * ASTR + h * 16;

    float c[2][8][4];
#pragma unroll
    for (int s = 0; s < 2; s++)
#pragma unroll
        for (int q = 0; q < 8; q++)
#pragma unroll
            for (int v = 0; v < 4; v++) c[s][q][v] = 0.f;

    // B prefetch: 4 x 16B per thread per tile, direct into padded tf32 layout.
#define PREFETCH_B(KT) do {                                                     \
        if ((KT) < NKT) {                                                       \
            const uint32_t bb = bs_base + (uint32_t)(((KT) & 1) * (BSZW * 4));  \
            const uint32_t* srcb = Wt + (size_t)(KT) * 32 * NVOCAB;             \
            _Pragma("unroll")                                                   \
            for (int j = 0; j < 4; j++) {                                       \
                int cc = t + 256 * j;                                           \
                int k = cc >> 5, nc = (cc & 31) * 4;                            \
                uint32_t dst = bb + (uint32_t)(k * BSTR + nc) * 4;              \
                const uint32_t* src = srcb + k * NVOCAB + nc;                   \
                asm volatile("cp.async.cg.shared.global [%0], [%1], 16;"        \
                             :: "r"(dst), "l"(src) : "memory");                 \
            }                                                                   \
        }                                                                       \
        asm volatile("cp.async.commit_group;" ::: "memory");                    \
    } while (0)

    PREFETCH_B(0);
    PREFETCH_B(1);

#pragma unroll 1
    for (int kt = 0; kt < NKT; kt++) {
        const int k0 = kt * 32;
        // Produce A tile: gather + add + exact gelu + tf32 (overlaps B arrival)
#pragma unroll
        for (int j = 0; j < 4; j++) {
            float4 vl = *reinterpret_cast<const float4*>(pL + k0 + 4 * j);
            float4 vr = *reinterpret_cast<const float4*>(pR + k0 + 4 * j);
            uint4 u;
            u.x = f2tf(gelu_exact(vl.x + vr.x));
            u.y = f2tf(gelu_exact(vl.y + vr.y));
            u.z = f2tf(gelu_exact(vl.z + vr.z));
            u.w = f2tf(gelu_exact(vl.w + vr.w));
            *reinterpret_cast<uint4*>(&A_s[aoff + 4 * j]) = u;
        }

        asm volatile("cp.async.wait_group 1;" ::: "memory");
        __syncthreads();

        uint32_t* Bp = Bs + (kt & 1) * BSZW;
        COMPUTE_TILE(A_s, Bp);
        __syncthreads();

        PREFETCH_B(kt + 2);
    }

    // Epilogue: out shape (BATCH, INST, NVOCAB) fp32
#pragma unroll
    for (int s = 0; s < 2; s++) {
        int rowb = mt * 128 + wm + s * 16 + g;
#pragma unroll
        for (int q = 0; q < 8; q++) {
            int col = wn + q * 8 + 2 * tg;
            *reinterpret_cast<float2*>(out + ((size_t)rowb * INST + inst) * NVOCAB + col) =
                make_float2(c[s][q][0], c[s][q][1]);
            *reinterpret_cast<float2*>(out + ((size_t)(rowb + 8) * INST + inst) * NVOCAB + col) =
                make_float2(c[s][q][2], c[s][q][3]);
        }
    }
}

// ---------------------------------------------------------------------------
extern "C" void kernel_launch(void* const* d_in, const int* in_sizes, int n_in,
                              void* d_out, int out_size)
{
    const int*   a  = (const int*)d_in[0];
    const float* El = (const float*)d_in[1];
    const float* Er = (const float*)d_in[2];
    const float* W1 = (const float*)d_in[3];
    const float* W2 = (const float*)d_in[4];
    float* out = (float*)d_out;

    static int configured = 0;
    if (!configured) {
        cudaFuncSetAttribute(phase1_kernel,
                             cudaFuncAttributeMaxDynamicSharedMemorySize, P1_SMEM);
        cudaFuncSetAttribute(phase2_kernel,
                             cudaFuncAttributeMaxDynamicSharedMemorySize, P2_SMEM);
        configured = 1;
    }

    // W2 -> tf32 (64*1024*128 / 1024 elems per block)
    w2t_kernel<<<(INST * HID * NVOCAB) / 1024, 256>>>(W2);

    dim3 g1(HID / 128, INST, 2);
    phase1_kernel<<<g1, 256, P1_SMEM>>>(El, Er, W1);

    dim3 g2(BATCH / 128, INST);
    phase2_kernel<<<g2, 256, P2_SMEM>>>(a, out);
}

// round 5
// speedup vs baseline: 1.7860x; 1.0207x over previous
#include <cuda_runtime.h>
#include <cuda_bf16.h>
#include <cstdint>
#include <math.h>

#define INST   64
#define NVOCAB 128
#define ED     256
#define HID    1024
#define BATCH  2048

// Precomputed HL[i] = E_l[i] @ W1[i], HR[i] = E_r[i] @ W1[i]  (fp32 scratch)
__device__ float g_HL[INST * NVOCAB * HID];
__device__ float g_HR[INST * NVOCAB * HID];
// W2 preconverted to tf32 bit patterns, layout [inst][k][n] (same as input)
__device__ uint32_t g_W2t[INST * HID * NVOCAB];

__device__ __forceinline__ uint32_t f2tf(float f) {
    uint32_t u;
    asm("cvt.rna.tf32.f32 %0, %1;" : "=r"(u) : "f"(f));
    return u;
}
__device__ __forceinline__ void mma8(float* c, const uint32_t* a, const uint32_t* b) {
    asm volatile(
        "mma.sync.aligned.m16n8k8.row.col.f32.tf32.tf32.f32 "
        "{%0,%1,%2,%3}, {%4,%5,%6,%7}, {%8,%9}, {%0,%1,%2,%3};"
        : "+f"(c[0]), "+f"(c[1]), "+f"(c[2]), "+f"(c[3])
        : "r"(a[0]), "r"(a[1]), "r"(a[2]), "r"(a[3]), "r"(b[0]), "r"(b[1]));
}
__device__ __forceinline__ float gelu_exact(float x) {
    return 0.5f * x * (1.0f + erff(x * 0.7071067811865476f));
}
__device__ __forceinline__ uint32_t smem_u32(const void* p) {
    uint32_t a;
    asm("{ .reg .u64 t; cvta.to.shared.u64 t, %1; cvt.u32.u64 %0, t; }" : "=r"(a) : "l"(p));
    return a;
}

// Shared tile strides (words). Conflict-free fragment loads:
//   A bank = (4*row + k) % 32, B bank = (8*k + n) % 32
#define ASTR 36
#define BSTR 136
#define ASZW (128 * ASTR)     // 4608 words
#define BSZW (32 * BSTR)      // 4352 words
#define NKT  (HID / 32)       // 32 k-tiles in phase 2
#define NKT1 (ED / 32)        // 8 k-tiles in phase 1
#define NSTG 3                // B pipeline depth

// 16 MMAs per 8-deep k-slice, 4 slices per 32-K tile.
#define COMPUTE_TILE(Ap, Bp)                                                    \
    _Pragma("unroll")                                                           \
    for (int ks = 0; ks < 4; ks++) {                                            \
        const int kk = ks * 8;                                                  \
        uint32_t af[2][4];                                                      \
        _Pragma("unroll")                                                       \
        for (int s = 0; s < 2; s++) {                                           \
            int r0 = wm + s * 16 + g;                                           \
            af[s][0] = (Ap)[r0 * ASTR + kk + tg];                               \
            af[s][1] = (Ap)[(r0 + 8) * ASTR + kk + tg];                         \
            af[s][2] = (Ap)[r0 * ASTR + kk + 4 + tg];                           \
            af[s][3] = (Ap)[(r0 + 8) * ASTR + kk + 4 + tg];                     \
        }                                                                       \
        uint32_t bf[8][2];                                                      \
        _Pragma("unroll")                                                       \
        for (int q = 0; q < 8; q++) {                                           \
            int nb = wn + q * 8 + g;                                            \
            bf[q][0] = (Bp)[(kk + tg) * BSTR + nb];                             \
            bf[q][1] = (Bp)[(kk + 4 + tg) * BSTR + nb];                         \
        }                                                                       \
        _Pragma("unroll")                                                       \
        for (int s = 0; s < 2; s++)                                             \
            _Pragma("unroll")                                                   \
            for (int q = 0; q < 8; q++)                                         \
                mma8(c[s][q], af[s], bf[q]);                                    \
    }

// ---------------------------------------------------------------------------
// Phase 0: W2 fp32 -> tf32 bit patterns (one-time, DRAM-bound ~11us)
// ---------------------------------------------------------------------------
__global__ __launch_bounds__(256) void w2t_kernel(const float* __restrict__ W2)
{
    size_t idx = ((size_t)blockIdx.x * 256 + threadIdx.x) * 4;
    float4 v = *reinterpret_cast<const float4*>(W2 + idx);
    *reinterpret_cast<uint4*>(g_W2t + idx) =
        make_uint4(f2tf(v.x), f2tf(v.y), f2tf(v.z), f2tf(v.w));
}

// ---------------------------------------------------------------------------
// Phase 1: HL/HR[i] = E[i] (128x256) @ W1[i] (256x1024), tf32 MMA, fp32 out
// cp.async-pipelined B (depth 3), recoalesced A. grid (8, 64, 2), 256 thr.
// ---------------------------------------------------------------------------
#define GEMM_SMEM ((ASZW + NSTG * BSZW) * 4)   // 70656 B -> 2 CTAs/SM

__global__ __launch_bounds__(256, 2) void phase1_kernel(
    const float* __restrict__ El, const float* __restrict__ Er,
    const float* __restrict__ W1)
{
    extern __shared__ uint32_t dsm[];
    uint32_t* A_s = dsm;
    uint32_t* Bs  = dsm + ASZW;
    const uint32_t bs_base = smem_u32(Bs);

    const int nt = blockIdx.x, inst = blockIdx.y, side = blockIdx.z;
    const float* E   = (side ? Er : El) + inst * NVOCAB * ED;
    float*       Hst = (side ? g_HR : g_HL) + inst * NVOCAB * HID + nt * 128;
    const float* W   = W1 + inst * ED * HID + nt * 128;

    const int t    = threadIdx.x;
    const int lane = t & 31, w = t >> 5;
    const int wm = (w & 3) * 32, wn = (w >> 2) * 64;
    const int g = lane >> 2, tg = lane & 3;
    // A-producer mapping: 8 lanes per row (nL=4 per LDG)
    const int r0a = t >> 3, c4 = (t & 7) * 4;

    float c[2][8][4];
#pragma unroll
    for (int s = 0; s < 2; s++)
#pragma unroll
        for (int q = 0; q < 8; q++)
#pragma unroll
            for (int v = 0; v < 4; v++) c[s][q][v] = 0.f;

#define PREFETCH_B1(KT) do {                                                    \
        if ((KT) < NKT1) {                                                      \
            const uint32_t bb = bs_base + (uint32_t)((((KT) % NSTG)) * (BSZW * 4)); \
            const float* srcb = W + (size_t)(KT) * 32 * HID;                    \
            _Pragma("unroll")                                                   \
            for (int j = 0; j < 4; j++) {                                       \
                int cc = t + 256 * j;                                           \
                int k = cc >> 5, nc = (cc & 31) * 4;                            \
                uint32_t dst = bb + (uint32_t)(k * BSTR + nc) * 4;              \
                const float* src = srcb + (size_t)k * HID + nc;                 \
                asm volatile("cp.async.cg.shared.global [%0], [%1], 16;"        \
                             :: "r"(dst), "l"(src) : "memory");                 \
            }                                                                   \
        }                                                                       \
        asm volatile("cp.async.commit_group;" ::: "memory");                    \
    } while (0)

    PREFETCH_B1(0); PREFETCH_B1(1); PREFETCH_B1(2);

#pragma unroll 1
    for (int kt = 0; kt < NKT1; kt++) {
        const int k0 = kt * 32;
        // Produce A tile: tf32 convert of E rows (cp.async-free: needs convert)
#pragma unroll
        for (int j = 0; j < 4; j++) {
            int row = r0a + 32 * j;
            float4 v = *reinterpret_cast<const float4*>(E + row * ED + k0 + c4);
            *reinterpret_cast<uint4*>(&A_s[row * ASTR + c4]) =
                make_uint4(f2tf(v.x), f2tf(v.y), f2tf(v.z), f2tf(v.w));
        }
        asm volatile("cp.async.wait_group %0;" :: "n"(NSTG - 1) : "memory");
        __syncthreads();

        // B arrived as raw fp32; convert in-place view: W1 fp32 == tf32? No —
        // MMA needs tf32 operands. Convert B during fragment load is not
        // possible, so convert B tile here cooperatively (LDS+cvt+STS would
        // double traffic). Instead: tf32 truncation for B is done by MMA HW?
        // It is NOT. => B must be pre-converted; see note below: we convert
        // here with a cheap pass (32 words/thread, conflict-free).
        {
            uint32_t* Bp = Bs + (kt % NSTG) * BSZW;
#pragma unroll
            for (int j = 0; j < 4; j++) {
                int cc = t + 256 * j;
                int k = cc >> 5, nc = (cc & 31) * 4;
                uint4* p = reinterpret_cast<uint4*>(&Bp[k * BSTR + nc]);
                uint4 u = *p;
                u.x = f2tf(__uint_as_float(u.x));
                u.y = f2tf(__uint_as_float(u.y));
                u.z = f2tf(__uint_as_float(u.z));
                u.w = f2tf(__uint_as_float(u.w));
                *p = u;
            }
            __syncthreads();
            COMPUTE_TILE(A_s, Bp);
        }
        __syncthreads();
        PREFETCH_B1(kt + NSTG);
    }

#pragma unroll
    for (int s = 0; s < 2; s++) {
        int row = wm + s * 16 + g;
#pragma unroll
        for (int q = 0; q < 8; q++) {
            int col = wn + q * 8 + 2 * tg;
            *reinterpret_cast<float2*>(Hst + row * HID + col) =
                make_float2(c[s][q][0], c[s][q][1]);
            *reinterpret_cast<float2*>(Hst + (row + 8) * HID + col) =
                make_float2(c[s][q][2], c[s][q][3]);
        }
    }
}

// ---------------------------------------------------------------------------
// Phase 2: out[b,i,:] = gelu(HL[i,a1[b],:] + HR[i,a2[b],:]) @ W2[i]
// Recoalesced gather (8 lanes/row), cp.async B pipeline depth 3, 2 CTAs/SM.
// grid (16 m-tiles, 64 instances), 256 threads.
// ---------------------------------------------------------------------------
__global__ __launch_bounds__(256, 2) void phase2_kernel(
    const int* __restrict__ a, float* __restrict__ out)
{
    extern __shared__ uint32_t dsm[];
    uint32_t* A_s = dsm;
    uint32_t* Bs  = dsm + ASZW;
    const uint32_t bs_base = smem_u32(Bs);

    const int mt = blockIdx.x, inst = blockIdx.y;
    const uint32_t* Wt = g_W2t + (size_t)inst * HID * NVOCAB;

    const int t    = threadIdx.x;
    const int lane = t & 31, w = t >> 5;
    const int wm = (w & 3) * 32, wn = (w >> 2) * 64;
    const int g = lane >> 2, tg = lane & 3;
    // A-producer mapping: row = (t>>3) + 32j, float4 col group c4
    const int r0a = t >> 3, c4 = (t & 7) * 4;

    // Hoist gather offsets (u32 byte offsets into g_HL/g_HR, < 32MB)
    uint32_t offL[4], offR[4];
#pragma unroll
    for (int j = 0; j < 4; j++) {
        int row = r0a + 32 * j;
        int b = mt * 128 + row;
        int i1 = a[2 * b], i2 = a[2 * b + 1];
        offL[j] = (uint32_t)(inst * NVOCAB + i1) * (HID * 4);
        offR[j] = (uint32_t)(inst * NVOCAB + i2) * (HID * 4);
    }
    const char* baseL = (const char*)g_HL;
    const char* baseR = (const char*)g_HR;

    float c[2][8][4];
#pragma unroll
    for (int s = 0; s < 2; s++)
#pragma unroll
        for (int q = 0; q < 8; q++)
#pragma unroll
            for (int v = 0; v < 4; v++) c[s][q][v] = 0.f;

#define PREFETCH_B2(KT) do {                                                    \
        if ((KT) < NKT) {                                                       \
            const uint32_t bb = bs_base + (uint32_t)((((KT) % NSTG)) * (BSZW * 4)); \
            const uint32_t* srcb = Wt + (size_t)(KT) * 32 * NVOCAB;             \
            _Pragma("unroll")                                                   \
            for (int j = 0; j < 4; j++) {                                       \
                int cc = t + 256 * j;                                           \
                int k = cc >> 5, nc = (cc & 31) * 4;                            \
                uint32_t dst = bb + (uint32_t)(k * BSTR + nc) * 4;              \
                const uint32_t* src = srcb + k * NVOCAB + nc;                   \
                asm volatile("cp.async.cg.shared.global [%0], [%1], 16;"        \
                             :: "r"(dst), "l"(src) : "memory");                 \
            }                                                                   \
        }                                                                       \
        asm volatile("cp.async.commit_group;" ::: "memory");                    \
    } while (0)

    PREFETCH_B2(0); PREFETCH_B2(1); PREFETCH_B2(2);

#pragma unroll 1
    for (int kt = 0; kt < NKT; kt++) {
        const uint32_t kb = (uint32_t)(kt * 32 + c4) * 4;   // byte offset in row
        // Produce A tile: gather + add + exact gelu + tf32 (recoalesced)
#pragma unroll
        for (int j = 0; j < 4; j++) {
            int row = r0a + 32 * j;
            float4 vl = *reinterpret_cast<const float4*>(baseL + offL[j] + kb);
            float4 vr = *reinterpret_cast<const float4*>(baseR + offR[j] + kb);
            uint4 u;
            u.x = f2tf(gelu_exact(vl.x + vr.x));
            u.y = f2tf(gelu_exact(vl.y + vr.y));
            u.z = f2tf(gelu_exact(vl.z + vr.z));
            u.w = f2tf(gelu_exact(vl.w + vr.w));
            *reinterpret_cast<uint4*>(&A_s[row * ASTR + c4]) = u;
        }

        asm volatile("cp.async.wait_group %0;" :: "n"(NSTG - 1) : "memory");
        __syncthreads();

        uint32_t* Bp = Bs + (kt % NSTG) * BSZW;
        COMPUTE_TILE(A_s, Bp);
        __syncthreads();

        PREFETCH_B2(kt + NSTG);
    }

    // Epilogue: out shape (BATCH, INST, NVOCAB) fp32
#pragma unroll
    for (int s = 0; s < 2; s++) {
        int rowb = mt * 128 + wm + s * 16 + g;
#pragma unroll
        for (int q = 0; q < 8; q++) {
            int col = wn + q * 8 + 2 * tg;
            *reinterpret_cast<float2*>(out + ((size_t)rowb * INST + inst) * NVOCAB + col) =
                make_float2(c[s][q][0], c[s][q][1]);
            *reinterpret_cast<float2*>(out + ((size_t)(rowb + 8) * INST + inst) * NVOCAB + col) =
                make_float2(c[s][q][2], c[s][q][3]);
        }
    }
}

// ---------------------------------------------------------------------------
extern "C" void kernel_launch(void* const* d_in, const int* in_sizes, int n_in,
                              void* d_out, int out_size)
{
    const int*   a  = (const int*)d_in[0];
    const float* El = (const float*)d_in[1];
    const float* Er = (const float*)d_in[2];
    const float* W1 = (const float*)d_in[3];
    const float* W2 = (const float*)d_in[4];
    float* out = (float*)d_out;

    static int configured = 0;
    if (!configured) {
        cudaFuncSetAttribute(phase1_kernel,
                             cudaFuncAttributeMaxDynamicSharedMemorySize, GEMM_SMEM);
        cudaFuncSetAttribute(phase2_kernel,
                             cudaFuncAttributeMaxDynamicSharedMemorySize, GEMM_SMEM);
        configured = 1;
    }

    // W2 -> tf32 bit patterns
    w2t_kernel<<<(INST * HID * NVOCAB) / 1024, 256>>>(W2);

    dim3 g1(HID / 128, INST, 2);
    phase1_kernel<<<g1, 256, GEMM_SMEM>>>(El, Er, W1);

    dim3 g2(BATCH / 128, INST);
    phase2_kernel<<<g2, 256, GEMM_SMEM>>>(a, out);
}